// round 17
// baseline (speedup 1.0000x reference)
#include <cuda_runtime.h>

typedef unsigned long long ull;
typedef unsigned int u32;

#define NROWS   16384
#define DIMP    1024
#define NCLS    10
#define IMG     784

#define NTILE   7                 // 7 tiles x 112 d = 784 = exactly the live ref support
#define TILEB   448               // 112 floats per row per tile
#define NSLOT   224               // 7 tiles x 32 ref slots (28 live + 4 zero)
#define REF_BYTES (NSLOT * 176)   // 39424
#define NSTAGE  2
#define WSTAGE  (4 * TILEB)       // per-warp stage: 2 rows x {re,im} x 448 B = 1792
#define Z_OFF   REF_BYTES
#define SMEM_TOTAL (Z_OFF + 8 * NSTAGE * WSTAGE)   // 39424 + 28672 = 68096

// Packed reference pairs (prologue output), dense layout:
// g_refp[(d>>2)*20 + p*4 + (d&3)] = ( ref[2p][d], ref[2p+1][d] )
__device__ ull g_refp[256 * 20];

// ---------- f32x2 helpers ----------
__device__ __forceinline__ ull pack2(float lo, float hi) {
    ull r;
    asm("mov.b64 %0, {%1, %2};" : "=l"(r) : "f"(lo), "f"(hi));
    return r;
}
__device__ __forceinline__ void unpack2(ull v, float& lo, float& hi) {
    asm("mov.b64 {%0, %1}, %2;" : "=f"(lo), "=f"(hi) : "l"(v));
}
__device__ __forceinline__ void fma2(ull& acc, ull a, ull b) {
    asm("fma.rn.f32x2 %0, %1, %2, %0;" : "+l"(acc) : "l"(a), "l"(b));
}
__device__ __forceinline__ void add2(ull& acc, ull a) {
    asm("add.rn.f32x2 %0, %1, %0;" : "+l"(acc) : "l"(a));
}

// ---------- cp.async helpers (per-warp private pipeline, no barriers) ----------
__device__ __forceinline__ u32 smem_u32(const void* p) {
    u32 a;
    asm("{ .reg .u64 t; cvta.to.shared.u64 t, %1; cvt.u32.u64 %0, t; }" : "=r"(a) : "l"(p));
    return a;
}
__device__ __forceinline__ void cp16(u32 dst, const void* src) {
    asm volatile("cp.async.cg.shared.global [%0], [%1], 16;" :: "r"(dst), "l"(src) : "memory");
}
__device__ __forceinline__ void cp_commit() {
    asm volatile("cp.async.commit_group;" ::: "memory");
}
__device__ __forceinline__ void cp_wait1() {
    asm volatile("cp.async.wait_group 1;" ::: "memory");
}

// ---------- prologue: block p normalizes classes 2p, 2p+1 and writes packed pairs ----------
__global__ void ref_pack_kernel(const float* __restrict__ canon) {
    __shared__ float v0[DIMP], v1[DIMP];
    __shared__ float wred[16];
    __shared__ float invs[2];
    const int p = blockIdx.x, t = threadIdx.x;
    const float* c0 = canon + (2 * p) * IMG;
    const float* c1 = canon + (2 * p + 1) * IMG;
    float s0 = 0.f, s1 = 0.f;
    for (int i = t; i < DIMP; i += 256) {
        float a = (i < IMG) ? c0[i] : 0.f;
        float b = (i < IMG) ? c1[i] : 0.f;
        v0[i] = a; v1[i] = b;
        s0 += a * a; s1 += b * b;
    }
    #pragma unroll
    for (int o = 16; o; o >>= 1) {
        s0 += __shfl_xor_sync(0xFFFFFFFFu, s0, o);
        s1 += __shfl_xor_sync(0xFFFFFFFFu, s1, o);
    }
    if ((t & 31) == 0) { wred[t >> 5] = s0; wred[8 + (t >> 5)] = s1; }
    __syncthreads();
    if (t == 0) {
        float a = 0.f, b = 0.f;
        #pragma unroll
        for (int i = 0; i < 8; i++) { a += wred[i]; b += wred[8 + i]; }
        invs[0] = 1.0f / sqrtf(a);
        invs[1] = 1.0f / sqrtf(b);
    }
    __syncthreads();
    const float i0 = invs[0], i1 = invs[1];
    for (int d = t; d < DIMP; d += 256)
        g_refp[(d >> 2) * 20 + p * 4 + (d & 3)] = pack2(v0[d] * i0, v1[d] * i1);
}

// ---------- main kernel ----------
// 256 threads = 8 warps, 2 rows/warp, grid 1024; 3 blocks/SM = 24 warps/SM.
// EXACT 112-d tiling: 7 tiles x 112 d = 784 = ref live support; no dead FMA
// or ref-LDS work anywhere. Lanes 0-27 own a d-quad per tile; lanes 28-31 read
// staged-zero ref (x finite z) -> contribute exactly 0.
// z via per-warp private 2-stage cp.async ring (distance-1, zero cross-warp sync).
__global__ __launch_bounds__(256, 3) void swap_test_kernel(
    const float* __restrict__ zre, const float* __restrict__ zim,
    float* __restrict__ out) {

    extern __shared__ __align__(16) char smem[];
    const u32 sbase = smem_u32(smem);
    const int tid  = threadIdx.x;
    const int lane = tid & 31;
    const int w    = tid >> 5;
    const int rowBase0 = blockIdx.x * 16;

    // stage packed ref: 224 slots of 176 B; slot s<28 of tile t holds live
    // group t*28+s, slots 28..31 hold zeros.
    {
        const float4* g4 = (const float4*)g_refp;
        const float4 zv = make_float4(0.f, 0.f, 0.f, 0.f);
        for (int c = tid; c < NSLOT * 10; c += 256) {
            const int q = c / 10;          // slot index 0..223
            const int r = c - q * 10;
            const int t = q >> 5;          // tile
            const int s = q & 31;          // slot within tile
            float4 v = (s < 28) ? g4[(t * 28 + s) * 10 + r] : zv;
            *((float4*)(smem + q * 176 + r * 16)) = v;
        }
    }

    // z sources: rows 2w, 2w+1 for re & im; lane covers 16 B of each 448 B tile-chunk
    const char* zrsrc = (const char*)(zre + (size_t)(rowBase0 + 2 * w) * DIMP) + lane * 16;
    const char* zisrc = (const char*)(zim + (size_t)(rowBase0 + 2 * w) * DIMP) + lane * 16;
    const u32 zst = sbase + Z_OFF + (u32)w * (NSTAGE * WSTAGE) + (u32)lane * 16;
    const bool cpon = (lane < 28);

    // prime tile 0 -> stage 0
    if (cpon) {
        cp16(zst,             zrsrc);
        cp16(zst + TILEB,     zrsrc + 4096);
        cp16(zst + 2 * TILEB, zisrc);
        cp16(zst + 3 * TILEB, zisrc + 4096);
    }
    cp_commit();

    __syncthreads();   // ref staging visible

    // acc A[p*4 + arr*2 + row]: f32x2 holds (class 2p, class 2p+1) partial sums
    ull A[20];
    #pragma unroll
    for (int i = 0; i < 20; i++) A[i] = 0ull;

    const char* rp = smem + (size_t)lane * 176;
    const u32 lclamp = (lane < 28 ? lane : 27) * 16;   // lanes 28-31: finite data x zero ref

    #pragma unroll
    for (int k = 0; k < NTILE; k++) {
        // distance-1 prefetch: tile k+1 into the other stage
        if (k < NTILE - 1 && cpon) {
            const int kk = k + 1;
            const u32 d = zst + (kk & 1) * WSTAGE;
            cp16(d,             zrsrc + kk * TILEB);
            cp16(d + TILEB,     zrsrc + kk * TILEB + 4096);
            cp16(d + 2 * TILEB, zisrc + kk * TILEB);
            cp16(d + 3 * TILEB, zisrc + kk * TILEB + 4096);
        }
        cp_commit();      // always commit (possibly empty) to keep count invariant
        cp_wait1();       // tile k's group complete (<=1 outstanding: tile k+1)

        const char* zb = smem + Z_OFF + (size_t)w * (NSTAGE * WSTAGE)
                              + (size_t)(k & 1) * WSTAGE + lclamp;
        const char* rk = rp + k * (32 * 176);

        #pragma unroll
        for (int h = 0; h < 2; h++) {      // component halves {x,y} then {z,w}
            float2 z0 = *(const float2*)(zb +             h * 8);   // row0 re
            float2 z1 = *(const float2*)(zb +     TILEB + h * 8);   // row1 re
            float2 z2 = *(const float2*)(zb + 2 * TILEB + h * 8);   // row0 im
            float2 z3 = *(const float2*)(zb + 3 * TILEB + h * 8);   // row1 im

            ull d0a = pack2(z0.x, z0.x), d0b = pack2(z0.y, z0.y);
            ull d1a = pack2(z1.x, z1.x), d1b = pack2(z1.y, z1.y);
            ull d2a = pack2(z2.x, z2.x), d2b = pack2(z2.y, z2.y);
            ull d3a = pack2(z3.x, z3.x), d3b = pack2(z3.y, z3.y);

            #pragma unroll
            for (int p = 0; p < 5; p++) {
                ulonglong2 f = *(const ulonglong2*)(rk + p * 32 + h * 16);
                fma2(A[p * 4 + 0], d0a, f.x); fma2(A[p * 4 + 0], d0b, f.y);  // row0 re
                fma2(A[p * 4 + 1], d2a, f.x); fma2(A[p * 4 + 1], d2b, f.y);  // row0 im
                fma2(A[p * 4 + 2], d1a, f.x); fma2(A[p * 4 + 2], d1b, f.y);  // row1 re
                fma2(A[p * 4 + 3], d3a, f.x); fma2(A[p * 4 + 3], d3b, f.y);  // row1 im
            }
        }
    }

    __syncthreads();   // all cp.async landed & all warps done with ref -> overlay

    // lane partials: 8 warps x 20 ull rows, stride 33 (bank-conflict-free STS.64)
    // 160 * 33 * 8 = 42,240 B <= 68,096 B block smem (ring area is dead now)
    ull* red = (ull*)smem;
    #pragma unroll
    for (int i = 0; i < 20; i++)
        red[(w * 20 + i) * 33 + lane] = A[i];
    __syncthreads();

    // 80 tasks: (warp w2, class-pair p, row j) -> 2 outputs each
    if (tid < 80) {
        const int w2 = tid / 10;
        const int q  = tid % 10;
        const int p  = q >> 1;
        const int j  = q & 1;
        const int mRe = w2 * 20 + p * 4 + j * 2;
        ull sre = 0ull, sim = 0ull;
        #pragma unroll
        for (int x = 0; x < 32; x++) {
            add2(sre, red[mRe * 33 + x]);
            add2(sim, red[(mRe + 1) * 33 + x]);
        }
        float reL, reH, imL, imH;
        unpack2(sre, reL, reH);
        unpack2(sim, imL, imH);
        const size_t row = (size_t)rowBase0 + (size_t)w2 * 2 + (size_t)j;
        out[row * NCLS + 2 * p]     = reL * reL + imL * imL;
        out[row * NCLS + 2 * p + 1] = reH * reH + imH * imH;
    }
}

extern "C" void kernel_launch(void* const* d_in, const int* in_sizes, int n_in,
                              void* d_out, int out_size) {
    const float* zre   = (const float*)d_in[0];
    const float* zim   = (const float*)d_in[1];
    const float* canon = (const float*)d_in[2];
    float* out = (float*)d_out;

    cudaFuncSetAttribute(swap_test_kernel,
                         cudaFuncAttributeMaxDynamicSharedMemorySize, SMEM_TOTAL);

    ref_pack_kernel<<<NCLS / 2, 256>>>(canon);
    swap_test_kernel<<<NROWS / 16, 256, SMEM_TOTAL>>>(zre, zim, out);
}